// round 3
// baseline (speedup 1.0000x reference)
#include <cuda_runtime.h>
#include <math.h>

#define BB 64
#define HH 1024
#define INN 1024
#define BH (BB * HH)

// Scratch (device globals — no allocations allowed).
// g_lin layout: [gate][b][h], gates: 0=i,1=f,2=o,3=q,4=k,5=v. k is scaled in-place by gates_kernel.
__device__ float g_lin[6 * BH];
__device__ float g_f[BH];
__device__ float g_o[BH];
__device__ float g_ip[BH];
__device__ float g_div[BB];

struct GemmArgs {
    const float* W[6];
    const float* bias[6];
};

// ---------------------------------------------------------------------------
// Kernel 1: six fused GEMMs.  Z[g][b][col] = sum_k x[b][k]*W_g[col][k] + b_g[col]
// Tile: 64 rows (all of B) x 32 cols per block. 256 threads as 16x16:
//   ty = tid/16 handles rows ty*4..ty*4+3 ; tx = tid%16 handles cols tx*2, tx*2+1.
// ---------------------------------------------------------------------------
__global__ __launch_bounds__(256) void gemm_kernel(const float* __restrict__ x, GemmArgs args) {
    __shared__ float xs[64][68];   // [row][k], padded so r and r+4 hit different banks
    __shared__ float Ws[64][34];   // [k][col], transposed for conflict-free reads

    const int g    = blockIdx.y;
    const int col0 = blockIdx.x * 32;
    const int tid  = threadIdx.x;
    const int tx   = tid & 15;
    const int ty   = tid >> 4;

    const float* __restrict__ W = args.W[g];

    float acc[4][2];
#pragma unroll
    for (int r = 0; r < 4; ++r) { acc[r][0] = 0.f; acc[r][1] = 0.f; }

    for (int k0 = 0; k0 < INN; k0 += 64) {
        // Load x tile: 64x64 floats = 1024 float4, 4 per thread.
#pragma unroll
        for (int i = 0; i < 4; ++i) {
            int s  = tid + i * 256;
            int r  = s >> 4;          // 0..63
            int c4 = s & 15;          // 0..15
            float4 v = *reinterpret_cast<const float4*>(&x[r * INN + k0 + c4 * 4]);
            *reinterpret_cast<float4*>(&xs[r][c4 * 4]) = v;
        }
        // Load W tile 32 cols x 64 k, store transposed: Ws[k][col].
#pragma unroll
        for (int i = 0; i < 2; ++i) {
            int s  = tid + i * 256;
            int r  = s >> 4;          // 0..31 (col within tile)
            int c4 = s & 15;
            float4 v = *reinterpret_cast<const float4*>(&W[(size_t)(col0 + r) * INN + k0 + c4 * 4]);
            Ws[c4 * 4 + 0][r] = v.x;
            Ws[c4 * 4 + 1][r] = v.y;
            Ws[c4 * 4 + 2][r] = v.z;
            Ws[c4 * 4 + 3][r] = v.w;
        }
        __syncthreads();

#pragma unroll 8
        for (int kk = 0; kk < 64; ++kk) {
            float2 w = *reinterpret_cast<const float2*>(&Ws[kk][tx * 2]);
            float xr0 = xs[ty * 4 + 0][kk];
            float xr1 = xs[ty * 4 + 1][kk];
            float xr2 = xs[ty * 4 + 2][kk];
            float xr3 = xs[ty * 4 + 3][kk];
            acc[0][0] += xr0 * w.x; acc[0][1] += xr0 * w.y;
            acc[1][0] += xr1 * w.x; acc[1][1] += xr1 * w.y;
            acc[2][0] += xr2 * w.x; acc[2][1] += xr2 * w.y;
            acc[3][0] += xr3 * w.x; acc[3][1] += xr3 * w.y;
        }
        __syncthreads();
    }

    const float* __restrict__ bias = args.bias[g];
    float b0 = bias[col0 + tx * 2 + 0];
    float b1 = bias[col0 + tx * 2 + 1];
    float* __restrict__ Z = g_lin + (size_t)g * BH;
#pragma unroll
    for (int r = 0; r < 4; ++r) {
        int row = ty * 4 + r;
        Z[row * HH + col0 + tx * 2 + 0] = acc[r][0] + b0;
        Z[row * HH + col0 + tx * 2 + 1] = acc[r][1] + b1;
    }
}

// ---------------------------------------------------------------------------
// Block reduction helper (sum). Valid result on thread 0.
// ---------------------------------------------------------------------------
__device__ __forceinline__ float block_reduce_sum(float v, float* sbuf) {
#pragma unroll
    for (int off = 16; off > 0; off >>= 1)
        v += __shfl_down_sync(0xffffffffu, v, off);
    int lane = threadIdx.x & 31;
    int w    = threadIdx.x >> 5;
    if (lane == 0) sbuf[w] = v;
    __syncthreads();
    if (w == 0) {
        v = (lane < ((int)blockDim.x >> 5)) ? sbuf[lane] : 0.f;
#pragma unroll
        for (int off = 4; off > 0; off >>= 1)
            v += __shfl_down_sync(0xffffffffu, v, off);
    }
    return v;
}

// ---------------------------------------------------------------------------
// Kernel 2: gates + n_t + m_t + divisor.  One block per batch row b.
// ---------------------------------------------------------------------------
__global__ __launch_bounds__(256) void gates_kernel(const float* __restrict__ n_in,
                                                    const float* __restrict__ m_in,
                                                    float* __restrict__ out) {
    __shared__ float sbuf[8];
    const int b   = blockIdx.x;
    const int tid = threadIdx.x;

    float* __restrict__ outN = out + (size_t)BH + (size_t)BB * HH * HH;
    float* __restrict__ outM = outN + BH;

    float local = 0.f;
#pragma unroll
    for (int j = 0; j < 4; ++j) {
        int h   = tid + j * 256;
        int idx = b * HH + h;
        float it = g_lin[0 * BH + idx];
        float ft = g_lin[1 * BH + idx];
        float ot = g_lin[2 * BH + idx];
        float qv = g_lin[3 * BH + idx];
        float kv = g_lin[4 * BH + idx] * 0.03125f;   // 1/sqrt(1024)

        float f_sig = 1.f / (1.f + expf(-ft));
        float o_sig = 1.f / (1.f + expf(-ot));
        // stable log-sigmoid
        float ls = (ft >= 0.f) ? -log1pf(expf(-ft)) : (ft - log1pf(expf(ft)));
        float mt = fmaxf(ls + m_in[idx], it);
        float ip = expf(it - mt);
        float nt = f_sig * n_in[idx] + ip * kv;

        g_f[idx]  = f_sig;
        g_o[idx]  = o_sig;
        g_ip[idx] = ip;
        g_lin[4 * BH + idx] = kv;  // scaled k, consumed by update_kernel

        outN[idx] = nt;
        outM[idx] = mt;
        local += nt * qv;
    }
    float tot = block_reduce_sum(local, sbuf);
    if (tid == 0) g_div[b] = fmaxf(fabsf(tot), 1.f);
}

// ---------------------------------------------------------------------------
// Kernel 3: fused C update + h.  One block per (b, row) — the HBM-bound pass.
//   C_t[b,r,j] = f[b,r]*C[b,r,j] + (ip[b,r]*v[b,r]) * k[b,j]
//   h[b,r]     = o[b,r] * dot(C_t[b,r,:], q[b,:]) / div[b]
// ---------------------------------------------------------------------------
__global__ __launch_bounds__(256) void update_kernel(const float* __restrict__ C,
                                                     float* __restrict__ out) {
    __shared__ float sbuf[8];
    const int row = blockIdx.x;        // 0 .. B*H-1
    const int b   = row >> 10;
    const int tid = threadIdx.x;

    const float4* __restrict__ Crow = reinterpret_cast<const float4*>(C + (size_t)row * HH);
    float4* __restrict__ Orow =
        reinterpret_cast<float4*>(out + (size_t)BH + (size_t)row * HH);
    const float4* __restrict__ krow =
        reinterpret_cast<const float4*>(g_lin + 4 * BH + b * HH);
    const float4* __restrict__ qrow =
        reinterpret_cast<const float4*>(g_lin + 3 * BH + b * HH);

    const float f   = g_f[row];
    const float ipv = g_ip[row] * g_lin[5 * BH + row];  // i' * v

    float4 c4 = Crow[tid];
    float4 k4 = krow[tid];
    float4 q4 = qrow[tid];

    float4 o;
    o.x = f * c4.x + ipv * k4.x;
    o.y = f * c4.y + ipv * k4.y;
    o.z = f * c4.z + ipv * k4.z;
    o.w = f * c4.w + ipv * k4.w;
    Orow[tid] = o;

    float dot = o.x * q4.x + o.y * q4.y + o.z * q4.z + o.w * q4.w;
    float tot = block_reduce_sum(dot, sbuf);
    if (tid == 0)
        out[row] = g_o[row] * tot / g_div[b];
}

// ---------------------------------------------------------------------------
// Launch
// ---------------------------------------------------------------------------
extern "C" void kernel_launch(void* const* d_in, const int* in_sizes, int n_in,
                              void* d_out, int out_size) {
    const float* x = (const float*)d_in[0];
    const float* C = (const float*)d_in[1];
    const float* n = (const float*)d_in[2];
    const float* m = (const float*)d_in[3];

    GemmArgs ga;
    for (int g = 0; g < 6; ++g) {
        ga.W[g]    = (const float*)d_in[4 + 2 * g];
        ga.bias[g] = (const float*)d_in[5 + 2 * g];
    }

    float* out = (float*)d_out;

    dim3 ggrid(HH / 32, 6);
    gemm_kernel<<<ggrid, 256>>>(x, ga);
    gates_kernel<<<BB, 256>>>(n, m, out);
    update_kernel<<<BB * HH, 256>>>(C, out);
}

// round 4
// speedup vs baseline: 1.3649x; 1.3649x over previous
#include <cuda_runtime.h>
#include <math.h>
#include <stdint.h>

#define BB 64
#define HH 1024
#define INN 1024
#define BH (BB * HH)

// Scratch (device globals — no allocations allowed).
// g_lin layout: [gate][b][h], gates: 0=i,1=f,2=o,3=q,4=k,5=v (raw GEMM, no bias).
// gates_kernel rewrites slot 3 (q+bias) and slot 4 ((k+bias)/32) in place.
__device__ float g_lin[6 * BH];
__device__ float g_f[BH];
__device__ float g_o[BH];
__device__ float g_ipv[BH];   // i' * v  (v with bias)
__device__ float g_div[BB];

struct GemmArgs { const float* W[6]; };
struct BiasArgs { const float* b[6]; };

__device__ __forceinline__ uint32_t f2tf(float f) {
    uint32_t r;
    asm("cvt.rna.tf32.f32 %0, %1;" : "=r"(r) : "f"(f));
    return r;
}

__device__ __forceinline__ void mma_tf32(float c[4],
                                         uint32_t a0, uint32_t a1, uint32_t a2, uint32_t a3,
                                         uint32_t b0, uint32_t b1) {
    asm("mma.sync.aligned.m16n8k8.row.col.f32.tf32.tf32.f32 "
        "{%0,%1,%2,%3},{%4,%5,%6,%7},{%8,%9},{%0,%1,%2,%3};"
        : "+f"(c[0]), "+f"(c[1]), "+f"(c[2]), "+f"(c[3])
        : "r"(a0), "r"(a1), "r"(a2), "r"(a3), "r"(b0), "r"(b1));
}

// ---------------------------------------------------------------------------
// Kernel 1: six fused GEMMs on tf32 tensor cores.
//   Z[g][m][n] = sum_k x[m][k] * W_g[n][k]      (bias added later in gates)
// Block tile: 64(M) x 32(N), BK=32, 256 threads = 8 warps as 4(M) x 2(N),
// warp tile 16x32... -> 16m x 16n (two n8 fragments). Double-buffered smem,
// XOR swizzle => conflict-free STS.128 fills and LDS.32 fragment loads.
// smem layout (tf32 bits): xs[m][k^((m&7)<<2)], ws[n][k^((n&7)<<2)], stride 32.
// ---------------------------------------------------------------------------
__global__ __launch_bounds__(256) void gemm_kernel(const float* __restrict__ x, GemmArgs args) {
    __shared__ uint32_t xs[2][64 * 32];
    __shared__ uint32_t ws[2][32 * 32];

    const int g    = blockIdx.y;
    const int n0   = blockIdx.x * 32;
    const float* __restrict__ W = args.W[g];

    const int tid  = threadIdx.x;
    const int lane = tid & 31;
    const int warp = tid >> 5;
    const int wm   = warp & 3;    // M-warp: rows wm*16
    const int wn   = warp >> 2;   // N-warp: cols wn*16

    const float4* __restrict__ x4 = reinterpret_cast<const float4*>(x);
    const float4* __restrict__ W4 = reinterpret_cast<const float4*>(W);

    const int fr = tid >> 3;      // fill row 0..31
    const int fc = tid & 7;       // fill float4-col 0..7

    // swizzled STS helpers
    auto stx = [&](int buf, int r, float4 v) {
        int idx = r * 32 + ((fc * 4) ^ ((r & 7) << 2));
        *reinterpret_cast<uint4*>(&xs[buf][idx]) =
            make_uint4(f2tf(v.x), f2tf(v.y), f2tf(v.z), f2tf(v.w));
    };
    auto stw = [&](int buf, int r, float4 v) {
        int idx = r * 32 + ((fc * 4) ^ ((r & 7) << 2));
        *reinterpret_cast<uint4*>(&ws[buf][idx]) =
            make_uint4(f2tf(v.x), f2tf(v.y), f2tf(v.z), f2tf(v.w));
    };

    // preload tile 0 (k0 = 0)
    {
        float4 px0 = x4[(size_t)fr * 256 + fc];
        float4 px1 = x4[(size_t)(fr + 32) * 256 + fc];
        float4 pw  = W4[(size_t)(n0 + fr) * 256 + fc];
        stx(0, fr, px0);
        stx(0, fr + 32, px1);
        stw(0, fr, pw);
    }
    __syncthreads();

    float acc0[4] = {0.f, 0.f, 0.f, 0.f};
    float acc1[4] = {0.f, 0.f, 0.f, 0.f};

    const int q  = lane >> 2;     // 0..7
    const int tt = lane & 3;      // 0..3
    const int sw = q << 2;

    const int arow0 = (wm * 16 + q) * 32;
    const int brow0 = (wn * 16 + q) * 32;

    int buf = 0;
    for (int t = 0; t < 32; ++t) {
        float4 nx0, nx1, nw;
        const bool more = (t < 31);
        if (more) {
            int k4n = (t + 1) * 8;
            nx0 = x4[(size_t)fr * 256 + k4n + fc];
            nx1 = x4[(size_t)(fr + 32) * 256 + k4n + fc];
            nw  = W4[(size_t)(n0 + fr) * 256 + k4n + fc];
        }

        const uint32_t* X  = xs[buf];
        const uint32_t* Wt = ws[buf];
#pragma unroll
        for (int kk = 0; kk < 4; ++kk) {
            int acol = ((kk * 8) + tt) ^ sw;
            uint32_t a0 = X[arow0 + acol];
            uint32_t a1 = X[arow0 + 8 * 32 + acol];
            uint32_t a2 = X[arow0 + (acol ^ 4)];
            uint32_t a3 = X[arow0 + 8 * 32 + (acol ^ 4)];
            uint32_t b0 = Wt[brow0 + acol];
            uint32_t b1 = Wt[brow0 + (acol ^ 4)];
            uint32_t b2 = Wt[brow0 + 8 * 32 + acol];
            uint32_t b3 = Wt[brow0 + 8 * 32 + (acol ^ 4)];
            mma_tf32(acc0, a0, a1, a2, a3, b0, b1);
            mma_tf32(acc1, a0, a1, a2, a3, b2, b3);
        }

        if (more) {
            stx(buf ^ 1, fr, nx0);
            stx(buf ^ 1, fr + 32, nx1);
            stw(buf ^ 1, fr, nw);
            __syncthreads();
        }
        buf ^= 1;
    }

    // epilogue: D fragment -> g_lin (c0,c1 at (row, 2t..2t+1); c2,c3 at row+8)
    float* __restrict__ Z = g_lin + (size_t)g * BH;
    const int r0 = wm * 16 + q;
    const int c0 = n0 + wn * 16 + 2 * tt;
    *reinterpret_cast<float2*>(&Z[(size_t)r0 * HH + c0])           = make_float2(acc0[0], acc0[1]);
    *reinterpret_cast<float2*>(&Z[(size_t)(r0 + 8) * HH + c0])     = make_float2(acc0[2], acc0[3]);
    *reinterpret_cast<float2*>(&Z[(size_t)r0 * HH + c0 + 8])       = make_float2(acc1[0], acc1[1]);
    *reinterpret_cast<float2*>(&Z[(size_t)(r0 + 8) * HH + c0 + 8]) = make_float2(acc1[2], acc1[3]);
}

// ---------------------------------------------------------------------------
// Kernel 2: bias + gates + n_t + m_t + divisor.  One block per batch row b.
// ---------------------------------------------------------------------------
__global__ __launch_bounds__(256) void gates_kernel(BiasArgs ba,
                                                    const float* __restrict__ n_in,
                                                    const float* __restrict__ m_in,
                                                    float* __restrict__ out) {
    __shared__ float sbuf[8];
    const int b   = blockIdx.x;
    const int tid = threadIdx.x;

    float* __restrict__ outN = out + (size_t)BH + (size_t)BB * HH * HH;
    float* __restrict__ outM = outN + BH;

    float local = 0.f;
#pragma unroll
    for (int j = 0; j < 4; ++j) {
        int h   = tid + j * 256;
        int idx = b * HH + h;
        float it = g_lin[0 * BH + idx] + ba.b[0][h];
        float ft = g_lin[1 * BH + idx] + ba.b[1][h];
        float ot = g_lin[2 * BH + idx] + ba.b[2][h];
        float qv = g_lin[3 * BH + idx] + ba.b[3][h];
        float kv = (g_lin[4 * BH + idx] + ba.b[4][h]) * 0.03125f;  // 1/sqrt(1024)
        float vv = g_lin[5 * BH + idx] + ba.b[5][h];

        float f_sig = 1.f / (1.f + expf(-ft));
        float o_sig = 1.f / (1.f + expf(-ot));
        float ls = (ft >= 0.f) ? -log1pf(expf(-ft)) : (ft - log1pf(expf(ft)));
        float mt = fmaxf(ls + m_in[idx], it);
        float ip = expf(it - mt);
        float nt = f_sig * n_in[idx] + ip * kv;

        g_f[idx]   = f_sig;
        g_o[idx]   = o_sig;
        g_ipv[idx] = ip * vv;
        g_lin[3 * BH + idx] = qv;   // biased q for update kernel
        g_lin[4 * BH + idx] = kv;   // biased+scaled k for update kernel

        outN[idx] = nt;
        outM[idx] = mt;
        local += nt * qv;
    }

#pragma unroll
    for (int off = 16; off > 0; off >>= 1)
        local += __shfl_down_sync(0xffffffffu, local, off);
    int lane = tid & 31, w = tid >> 5;
    if (lane == 0) sbuf[w] = local;
    __syncthreads();
    if (w == 0) {
        float v = (lane < 8) ? sbuf[lane] : 0.f;
#pragma unroll
        for (int off = 4; off > 0; off >>= 1)
            v += __shfl_down_sync(0xffffffffu, v, off);
        if (lane == 0) g_div[b] = fmaxf(fabsf(v), 1.f);
    }
}

// ---------------------------------------------------------------------------
// Kernel 3: fused C update + h.  One warp per row, 8 rows per block.
//   C_t[b,r,j] = f[b,r]*C[b,r,j] + ipv[b,r] * k[b,j]
//   h[b,r]     = o[b,r] * dot(C_t[b,r,:], q[b,:]) / div[b]
// k/q rows staged in smem (shared by all 8 warps); C streamed with .cs hints.
// ---------------------------------------------------------------------------
__global__ __launch_bounds__(256) void update_kernel(const float* __restrict__ C,
                                                     float* __restrict__ out) {
    __shared__ float4 ks[256], qs[256];
    const int tid  = threadIdx.x;
    const int lane = tid & 31;
    const int b    = blockIdx.x >> 7;               // 128 blocks per batch
    const int row  = blockIdx.x * 8 + (tid >> 5);   // this warp's row

    ks[tid] = reinterpret_cast<const float4*>(g_lin + 4 * BH + b * HH)[tid];
    qs[tid] = reinterpret_cast<const float4*>(g_lin + 3 * BH + b * HH)[tid];
    __syncthreads();

    const float f   = g_f[row];
    const float ipv = g_ipv[row];

    const float4* __restrict__ Cr = reinterpret_cast<const float4*>(C + (size_t)row * HH);
    float4* __restrict__ Or = reinterpret_cast<float4*>(out + (size_t)BH + (size_t)row * HH);

    float4 c4[8];
#pragma unroll
    for (int j = 0; j < 8; ++j)
        c4[j] = __ldcs(Cr + j * 32 + lane);

    float dot = 0.f;
#pragma unroll
    for (int j = 0; j < 8; ++j) {
        float4 k4 = ks[j * 32 + lane];
        float4 q4 = qs[j * 32 + lane];
        float4 o;
        o.x = fmaf(f, c4[j].x, ipv * k4.x);
        o.y = fmaf(f, c4[j].y, ipv * k4.y);
        o.z = fmaf(f, c4[j].z, ipv * k4.z);
        o.w = fmaf(f, c4[j].w, ipv * k4.w);
        __stcs(Or + j * 32 + lane, o);
        dot += o.x * q4.x + o.y * q4.y + o.z * q4.z + o.w * q4.w;
    }

#pragma unroll
    for (int off = 16; off > 0; off >>= 1)
        dot += __shfl_down_sync(0xffffffffu, dot, off);
    if (lane == 0)
        out[row] = g_o[row] * dot / g_div[b];
}

// ---------------------------------------------------------------------------
// Launch
// ---------------------------------------------------------------------------
extern "C" void kernel_launch(void* const* d_in, const int* in_sizes, int n_in,
                              void* d_out, int out_size) {
    const float* x = (const float*)d_in[0];
    const float* C = (const float*)d_in[1];
    const float* n = (const float*)d_in[2];
    const float* m = (const float*)d_in[3];

    GemmArgs ga;
    BiasArgs ba;
    for (int g = 0; g < 6; ++g) {
        ga.W[g] = (const float*)d_in[4 + 2 * g];
        ba.b[g] = (const float*)d_in[5 + 2 * g];
    }

    float* out = (float*)d_out;

    gemm_kernel<<<dim3(32, 6), 256>>>(x, ga);
    gates_kernel<<<BB, 256>>>(ba, n, m, out);
    update_kernel<<<BB * HH / 8, 256>>>(C, out);
}

// round 5
// speedup vs baseline: 1.7060x; 1.2499x over previous
#include <cuda_runtime.h>
#include <math.h>
#include <stdint.h>

#define BB 64
#define HH 1024
#define INN 1024
#define BH (BB * HH)
#define KSPLIT 4
#define KSLICE (INN / KSPLIT)   // 256

// Scratch (device globals — no allocations allowed).
// g_part: [kslice][gate][b][h] raw GEMM partial sums (no bias).
// g_lin : [gate][b][h]; gates_kernel writes biased q into slot 3, biased+scaled k into slot 4.
__device__ float g_part[KSPLIT * 6 * BH];
__device__ float g_lin[6 * BH];
__device__ float g_f[BH];
__device__ float g_o[BH];
__device__ float g_ipv[BH];   // i' * v  (v with bias)
__device__ float g_div[BB];

struct GemmArgs { const float* W[6]; };
struct BiasArgs { const float* b[6]; };

__device__ __forceinline__ uint32_t f2tf(float f) {
    uint32_t r;
    asm("cvt.rna.tf32.f32 %0, %1;" : "=r"(r) : "f"(f));
    return r;
}

__device__ __forceinline__ void mma_tf32(float c[4],
                                         uint32_t a0, uint32_t a1, uint32_t a2, uint32_t a3,
                                         uint32_t b0, uint32_t b1) {
    asm("mma.sync.aligned.m16n8k8.row.col.f32.tf32.tf32.f32 "
        "{%0,%1,%2,%3},{%4,%5,%6,%7},{%8,%9},{%0,%1,%2,%3};"
        : "+f"(c[0]), "+f"(c[1]), "+f"(c[2]), "+f"(c[3])
        : "r"(a0), "r"(a1), "r"(a2), "r"(a3), "r"(b0), "r"(b1));
}

// ---------------------------------------------------------------------------
// Kernel 1: six fused GEMMs on tf32 tensor cores, split-K=4.
//   part[z][g][m][n] = sum_{k in slice z} x[m][k] * W_g[n][k]
// Block tile: 64(M) x 32(N) x 256(Kslice). 256 threads = 8 warps (4M x 2N),
// warp tile 16x16. Double-buffered smem, XOR swizzle, BK=32 per stage.
// ---------------------------------------------------------------------------
__global__ __launch_bounds__(256) void gemm_kernel(const float* __restrict__ x, GemmArgs args) {
    __shared__ uint32_t xs[2][64 * 32];
    __shared__ uint32_t ws[2][32 * 32];

    const int g    = blockIdx.y;
    const int n0   = blockIdx.x * 32;
    const int z    = blockIdx.z;              // K slice
    const int kf0  = z * (KSLICE / 4);        // base in float4 units (64)
    const float* __restrict__ W = args.W[g];

    const int tid  = threadIdx.x;
    const int lane = tid & 31;
    const int warp = tid >> 5;
    const int wm   = warp & 3;    // M-warp: rows wm*16
    const int wn   = warp >> 2;   // N-warp: cols wn*16

    const float4* __restrict__ x4 = reinterpret_cast<const float4*>(x);
    const float4* __restrict__ W4 = reinterpret_cast<const float4*>(W);

    const int fr = tid >> 3;      // fill row 0..31
    const int fc = tid & 7;       // fill float4-col 0..7

    auto stx = [&](int buf, int r, float4 v) {
        int idx = r * 32 + ((fc * 4) ^ ((r & 7) << 2));
        *reinterpret_cast<uint4*>(&xs[buf][idx]) =
            make_uint4(f2tf(v.x), f2tf(v.y), f2tf(v.z), f2tf(v.w));
    };
    auto stw = [&](int buf, int r, float4 v) {
        int idx = r * 32 + ((fc * 4) ^ ((r & 7) << 2));
        *reinterpret_cast<uint4*>(&ws[buf][idx]) =
            make_uint4(f2tf(v.x), f2tf(v.y), f2tf(v.z), f2tf(v.w));
    };

    // preload tile 0 of this K slice
    {
        float4 px0 = x4[(size_t)fr * 256 + kf0 + fc];
        float4 px1 = x4[(size_t)(fr + 32) * 256 + kf0 + fc];
        float4 pw  = W4[(size_t)(n0 + fr) * 256 + kf0 + fc];
        stx(0, fr, px0);
        stx(0, fr + 32, px1);
        stw(0, fr, pw);
    }
    __syncthreads();

    float acc0[4] = {0.f, 0.f, 0.f, 0.f};
    float acc1[4] = {0.f, 0.f, 0.f, 0.f};

    const int q  = lane >> 2;     // 0..7
    const int tt = lane & 3;      // 0..3
    const int sw = q << 2;

    const int arow0 = (wm * 16 + q) * 32;
    const int brow0 = (wn * 16 + q) * 32;

    const int NT = KSLICE / 32;   // 8 stages
    int buf = 0;
    for (int t = 0; t < NT; ++t) {
        float4 nx0, nx1, nw;
        const bool more = (t < NT - 1);
        if (more) {
            int k4n = kf0 + (t + 1) * 8;
            nx0 = x4[(size_t)fr * 256 + k4n + fc];
            nx1 = x4[(size_t)(fr + 32) * 256 + k4n + fc];
            nw  = W4[(size_t)(n0 + fr) * 256 + k4n + fc];
        }

        const uint32_t* X  = xs[buf];
        const uint32_t* Wt = ws[buf];
#pragma unroll
        for (int kk = 0; kk < 4; ++kk) {
            int acol = ((kk * 8) + tt) ^ sw;
            uint32_t a0 = X[arow0 + acol];
            uint32_t a1 = X[arow0 + 8 * 32 + acol];
            uint32_t a2 = X[arow0 + (acol ^ 4)];
            uint32_t a3 = X[arow0 + 8 * 32 + (acol ^ 4)];
            uint32_t b0 = Wt[brow0 + acol];
            uint32_t b1 = Wt[brow0 + (acol ^ 4)];
            uint32_t b2 = Wt[brow0 + 8 * 32 + acol];
            uint32_t b3 = Wt[brow0 + 8 * 32 + (acol ^ 4)];
            mma_tf32(acc0, a0, a1, a2, a3, b0, b1);
            mma_tf32(acc1, a0, a1, a2, a3, b2, b3);
        }

        if (more) {
            stx(buf ^ 1, fr, nx0);
            stx(buf ^ 1, fr + 32, nx1);
            stw(buf ^ 1, fr, nw);
            __syncthreads();
        }
        buf ^= 1;
    }

    // epilogue: write partials for this K slice
    float* __restrict__ Z = g_part + ((size_t)z * 6 + g) * BH;
    const int r0 = wm * 16 + q;
    const int c0 = n0 + wn * 16 + 2 * tt;
    *reinterpret_cast<float2*>(&Z[(size_t)r0 * HH + c0])           = make_float2(acc0[0], acc0[1]);
    *reinterpret_cast<float2*>(&Z[(size_t)(r0 + 8) * HH + c0])     = make_float2(acc0[2], acc0[3]);
    *reinterpret_cast<float2*>(&Z[(size_t)r0 * HH + c0 + 8])       = make_float2(acc1[0], acc1[1]);
    *reinterpret_cast<float2*>(&Z[(size_t)(r0 + 8) * HH + c0 + 8]) = make_float2(acc1[2], acc1[3]);
}

// ---------------------------------------------------------------------------
// Kernel 2: fold split-K partials + bias + gates + n_t + m_t + divisor.
// One block per batch row b.
// ---------------------------------------------------------------------------
__global__ __launch_bounds__(256) void gates_kernel(BiasArgs ba,
                                                    const float* __restrict__ n_in,
                                                    const float* __restrict__ m_in,
                                                    float* __restrict__ out) {
    __shared__ float sbuf[8];
    const int b   = blockIdx.x;
    const int tid = threadIdx.x;

    float* __restrict__ outN = out + (size_t)BH + (size_t)BB * HH * HH;
    float* __restrict__ outM = outN + BH;

    float local = 0.f;
#pragma unroll
    for (int j = 0; j < 4; ++j) {
        int h   = tid + j * 256;
        int idx = b * HH + h;

        float z[6];
#pragma unroll
        for (int g = 0; g < 6; ++g) {
            float s = ba.b[g][h];
#pragma unroll
            for (int zz = 0; zz < KSPLIT; ++zz)
                s += g_part[((size_t)zz * 6 + g) * BH + idx];
            z[g] = s;
        }
        float it = z[0];
        float ft = z[1];
        float ot = z[2];
        float qv = z[3];
        float kv = z[4] * 0.03125f;   // 1/sqrt(1024)
        float vv = z[5];

        float f_sig = 1.f / (1.f + expf(-ft));
        float o_sig = 1.f / (1.f + expf(-ot));
        float ls = (ft >= 0.f) ? -log1pf(expf(-ft)) : (ft - log1pf(expf(ft)));
        float mt = fmaxf(ls + m_in[idx], it);
        float ip = expf(it - mt);
        float nt = f_sig * n_in[idx] + ip * kv;

        g_f[idx]   = f_sig;
        g_o[idx]   = o_sig;
        g_ipv[idx] = ip * vv;
        g_lin[3 * BH + idx] = qv;   // biased q for update kernel
        g_lin[4 * BH + idx] = kv;   // biased+scaled k for update kernel

        outN[idx] = nt;
        outM[idx] = mt;
        local += nt * qv;
    }

#pragma unroll
    for (int off = 16; off > 0; off >>= 1)
        local += __shfl_down_sync(0xffffffffu, local, off);
    int lane = tid & 31, w = tid >> 5;
    if (lane == 0) sbuf[w] = local;
    __syncthreads();
    if (w == 0) {
        float v = (lane < 8) ? sbuf[lane] : 0.f;
#pragma unroll
        for (int off = 4; off > 0; off >>= 1)
            v += __shfl_down_sync(0xffffffffu, v, off);
        if (lane == 0) g_div[b] = fmaxf(fabsf(v), 1.f);
    }
}

// ---------------------------------------------------------------------------
// Kernel 3: fused C update + h.  One warp per row, 8 rows per block.
//   C_t[b,r,j] = f[b,r]*C[b,r,j] + ipv[b,r] * k[b,j]
//   h[b,r]     = o[b,r] * dot(C_t[b,r,:], q[b,:]) / div[b]
// ---------------------------------------------------------------------------
__global__ __launch_bounds__(256) void update_kernel(const float* __restrict__ C,
                                                     float* __restrict__ out) {
    __shared__ float4 ks[256], qs[256];
    const int tid  = threadIdx.x;
    const int lane = tid & 31;
    const int b    = blockIdx.x >> 7;               // 128 blocks per batch
    const int row  = blockIdx.x * 8 + (tid >> 5);   // this warp's row

    ks[tid] = reinterpret_cast<const float4*>(g_lin + 4 * BH + b * HH)[tid];
    qs[tid] = reinterpret_cast<const float4*>(g_lin + 3 * BH + b * HH)[tid];
    __syncthreads();

    const float f   = g_f[row];
    const float ipv = g_ipv[row];

    const float4* __restrict__ Cr = reinterpret_cast<const float4*>(C + (size_t)row * HH);
    float4* __restrict__ Or = reinterpret_cast<float4*>(out + (size_t)BH + (size_t)row * HH);

    float4 c4[8];
#pragma unroll
    for (int j = 0; j < 8; ++j)
        c4[j] = __ldcs(Cr + j * 32 + lane);

    float dot = 0.f;
#pragma unroll
    for (int j = 0; j < 8; ++j) {
        float4 k4 = ks[j * 32 + lane];
        float4 q4 = qs[j * 32 + lane];
        float4 o;
        o.x = fmaf(f, c4[j].x, ipv * k4.x);
        o.y = fmaf(f, c4[j].y, ipv * k4.y);
        o.z = fmaf(f, c4[j].z, ipv * k4.z);
        o.w = fmaf(f, c4[j].w, ipv * k4.w);
        __stcs(Or + j * 32 + lane, o);
        dot = fmaf(o.x, q4.x, dot);
        dot = fmaf(o.y, q4.y, dot);
        dot = fmaf(o.z, q4.z, dot);
        dot = fmaf(o.w, q4.w, dot);
    }

#pragma unroll
    for (int off = 16; off > 0; off >>= 1)
        dot += __shfl_down_sync(0xffffffffu, dot, off);
    if (lane == 0)
        out[row] = g_o[row] * dot / g_div[b];
}

// ---------------------------------------------------------------------------
// Launch
// ---------------------------------------------------------------------------
extern "C" void kernel_launch(void* const* d_in, const int* in_sizes, int n_in,
                              void* d_out, int out_size) {
    const float* x = (const float*)d_in[0];
    const float* C = (const float*)d_in[1];
    const float* n = (const float*)d_in[2];
    const float* m = (const float*)d_in[3];

    GemmArgs ga;
    BiasArgs ba;
    for (int g = 0; g < 6; ++g) {
        ga.W[g] = (const float*)d_in[4 + 2 * g];
        ba.b[g] = (const float*)d_in[5 + 2 * g];
    }

    float* out = (float*)d_out;

    gemm_kernel<<<dim3(32, 6, KSPLIT), 256>>>(x, ga);
    gates_kernel<<<BB, 256>>>(ba, n, m, out);
    update_kernel<<<BB * HH / 8, 256>>>(C, out);
}

// round 6
// speedup vs baseline: 1.7626x; 1.0332x over previous
#include <cuda_runtime.h>
#include <math.h>
#include <stdint.h>

#define BB 64
#define HH 1024
#define INN 1024
#define BH (BB * HH)
#define KSPLIT 8
#define KSLICE (INN / KSPLIT)   // 128
#define NT (KSLICE / 32)        // 4 stages of BK=32

// Scratch (device globals — no allocations allowed).
// g_part: [kslice][gate][b][h] raw GEMM partial sums (no bias).
// g_lin : slot 3 = biased q, slot 4 = biased+scaled k (written by gates_kernel).
__device__ float g_part[KSPLIT * 6 * BH];
__device__ float g_lin[6 * BH];
__device__ float g_f[BH];
__device__ float g_o[BH];
__device__ float g_ipv[BH];   // i' * v  (v with bias)
__device__ float g_div[BB];

struct GemmArgs { const float* W[6]; };
struct BiasArgs { const float* b[6]; };

__device__ __forceinline__ uint32_t f2tf(float f) {
    uint32_t r;
    asm("cvt.rna.tf32.f32 %0, %1;" : "=r"(r) : "f"(f));
    return r;
}

__device__ __forceinline__ void mma_tf32(float c[4],
                                         uint32_t a0, uint32_t a1, uint32_t a2, uint32_t a3,
                                         uint32_t b0, uint32_t b1) {
    asm("mma.sync.aligned.m16n8k8.row.col.f32.tf32.tf32.f32 "
        "{%0,%1,%2,%3},{%4,%5,%6,%7},{%8,%9},{%0,%1,%2,%3};"
        : "+f"(c[0]), "+f"(c[1]), "+f"(c[2]), "+f"(c[3])
        : "r"(a0), "r"(a1), "r"(a2), "r"(a3), "r"(b0), "r"(b1));
}

// ---------------------------------------------------------------------------
// Kernel 1: six fused GEMMs on tf32 tensor cores, split-K=8.
// Block tile 64(M) x 128(N) x 128(Kslice); 8 warps as 2(M) x 4(N),
// warp tile 32x32 (2 m16-frags x 4 n8-frags = 8 MMAs / kk, 16 LDS / kk).
// Double-buffered smem, XOR swizzle, K loop fully unrolled (buf compile-time).
// ---------------------------------------------------------------------------
__global__ __launch_bounds__(256, 3) void gemm_kernel(const float* __restrict__ x, GemmArgs args) {
    __shared__ uint32_t xs[2][64 * 32];    // 16 KB
    __shared__ uint32_t ws[2][128 * 32];   // 32 KB

    const int g    = blockIdx.y;
    const int n0   = blockIdx.x * 128;
    const int z    = blockIdx.z;
    const int kf0  = z * (KSLICE / 4);     // base in float4 units (32)
    const float* __restrict__ W = args.W[g];

    const int tid  = threadIdx.x;
    const int lane = tid & 31;
    const int warp = tid >> 5;
    const int wm   = warp & 1;    // M-warp: rows wm*32
    const int wn   = warp >> 1;   // N-warp: cols wn*32

    const float4* __restrict__ x4 = reinterpret_cast<const float4*>(x);
    const float4* __restrict__ W4 = reinterpret_cast<const float4*>(W);

    const int fr = tid >> 3;      // fill row 0..31
    const int fc = tid & 7;       // fill float4-col 0..7
    const int fsw = (fc * 4) ^ ((fr & 7) << 2);  // row-xor swizzle (same for r, r+32, ...)

    auto cvt4 = [](float4 v) {
        return make_uint4(f2tf(v.x), f2tf(v.y), f2tf(v.z), f2tf(v.w));
    };

    // --- preload stage 0 ---
    {
        float4 px0 = x4[(size_t)fr * 256 + kf0 + fc];
        float4 px1 = x4[(size_t)(fr + 32) * 256 + kf0 + fc];
        float4 pw0 = W4[(size_t)(n0 + fr) * 256 + kf0 + fc];
        float4 pw1 = W4[(size_t)(n0 + fr + 32) * 256 + kf0 + fc];
        float4 pw2 = W4[(size_t)(n0 + fr + 64) * 256 + kf0 + fc];
        float4 pw3 = W4[(size_t)(n0 + fr + 96) * 256 + kf0 + fc];
        *reinterpret_cast<uint4*>(&xs[0][fr * 32 + fsw])        = cvt4(px0);
        *reinterpret_cast<uint4*>(&xs[0][(fr + 32) * 32 + fsw]) = cvt4(px1);
        *reinterpret_cast<uint4*>(&ws[0][fr * 32 + fsw])        = cvt4(pw0);
        *reinterpret_cast<uint4*>(&ws[0][(fr + 32) * 32 + fsw]) = cvt4(pw1);
        *reinterpret_cast<uint4*>(&ws[0][(fr + 64) * 32 + fsw]) = cvt4(pw2);
        *reinterpret_cast<uint4*>(&ws[0][(fr + 96) * 32 + fsw]) = cvt4(pw3);
    }
    __syncthreads();

    float acc[2][4][4];
#pragma unroll
    for (int i = 0; i < 2; ++i)
#pragma unroll
        for (int j = 0; j < 4; ++j)
#pragma unroll
            for (int l = 0; l < 4; ++l) acc[i][j][l] = 0.f;

    const int q  = lane >> 2;     // 0..7
    const int tt = lane & 3;      // 0..3
    const int sw = q << 2;

    // fragment column offsets (loop-invariant)
    int acol[4], acolx[4];
#pragma unroll
    for (int kk = 0; kk < 4; ++kk) {
        acol[kk]  = ((kk * 8) + tt) ^ sw;
        acolx[kk] = acol[kk] ^ 4;
    }
    const int arow = (wm * 32 + q) * 32;   // + {0,8,16,24}*32 row groups
    const int brow = (wn * 32 + q) * 32;

#pragma unroll
    for (int t = 0; t < NT; ++t) {
        const int buf = t & 1;

        // prefetch next stage (compile-time guard)
        float4 px0, px1, pw0, pw1, pw2, pw3;
        if (t < NT - 1) {
            int k4n = kf0 + (t + 1) * 8;
            px0 = x4[(size_t)fr * 256 + k4n + fc];
            px1 = x4[(size_t)(fr + 32) * 256 + k4n + fc];
            pw0 = W4[(size_t)(n0 + fr) * 256 + k4n + fc];
            pw1 = W4[(size_t)(n0 + fr + 32) * 256 + k4n + fc];
            pw2 = W4[(size_t)(n0 + fr + 64) * 256 + k4n + fc];
            pw3 = W4[(size_t)(n0 + fr + 96) * 256 + k4n + fc];
        }

        const uint32_t* __restrict__ X  = xs[buf];
        const uint32_t* __restrict__ Wt = ws[buf];
#pragma unroll
        for (int kk = 0; kk < 4; ++kk) {
            const int c = acol[kk], cx = acolx[kk];
            // A: two m16 fragments (rows wm*32 + {0,8} and {16,24})
            uint32_t a00 = X[arow + c];
            uint32_t a01 = X[arow + 8 * 32 + c];
            uint32_t a02 = X[arow + cx];
            uint32_t a03 = X[arow + 8 * 32 + cx];
            uint32_t a10 = X[arow + 16 * 32 + c];
            uint32_t a11 = X[arow + 24 * 32 + c];
            uint32_t a12 = X[arow + 16 * 32 + cx];
            uint32_t a13 = X[arow + 24 * 32 + cx];
            // B: four n8 fragments (cols wn*32 + {0,8,16,24})
            uint32_t b00 = Wt[brow + c],           b01 = Wt[brow + cx];
            uint32_t b10 = Wt[brow + 8 * 32 + c],  b11 = Wt[brow + 8 * 32 + cx];
            uint32_t b20 = Wt[brow + 16 * 32 + c], b21 = Wt[brow + 16 * 32 + cx];
            uint32_t b30 = Wt[brow + 24 * 32 + c], b31 = Wt[brow + 24 * 32 + cx];

            mma_tf32(acc[0][0], a00, a01, a02, a03, b00, b01);
            mma_tf32(acc[0][1], a00, a01, a02, a03, b10, b11);
            mma_tf32(acc[0][2], a00, a01, a02, a03, b20, b21);
            mma_tf32(acc[0][3], a00, a01, a02, a03, b30, b31);
            mma_tf32(acc[1][0], a10, a11, a12, a13, b00, b01);
            mma_tf32(acc[1][1], a10, a11, a12, a13, b10, b11);
            mma_tf32(acc[1][2], a10, a11, a12, a13, b20, b21);
            mma_tf32(acc[1][3], a10, a11, a12, a13, b30, b31);
        }

        if (t < NT - 1) {
            const int nb = buf ^ 1;
            *reinterpret_cast<uint4*>(&xs[nb][fr * 32 + fsw])        = cvt4(px0);
            *reinterpret_cast<uint4*>(&xs[nb][(fr + 32) * 32 + fsw]) = cvt4(px1);
            *reinterpret_cast<uint4*>(&ws[nb][fr * 32 + fsw])        = cvt4(pw0);
            *reinterpret_cast<uint4*>(&ws[nb][(fr + 32) * 32 + fsw]) = cvt4(pw1);
            *reinterpret_cast<uint4*>(&ws[nb][(fr + 64) * 32 + fsw]) = cvt4(pw2);
            *reinterpret_cast<uint4*>(&ws[nb][(fr + 96) * 32 + fsw]) = cvt4(pw3);
            __syncthreads();
        }
    }

    // epilogue: write partials
    float* __restrict__ Z = g_part + ((size_t)z * 6 + g) * BH;
#pragma unroll
    for (int fm = 0; fm < 2; ++fm) {
#pragma unroll
        for (int fn = 0; fn < 4; ++fn) {
            const int r0 = wm * 32 + fm * 16 + q;
            const int c0 = n0 + wn * 32 + fn * 8 + 2 * tt;
            *reinterpret_cast<float2*>(&Z[(size_t)r0 * HH + c0]) =
                make_float2(acc[fm][fn][0], acc[fm][fn][1]);
            *reinterpret_cast<float2*>(&Z[(size_t)(r0 + 8) * HH + c0]) =
                make_float2(acc[fm][fn][2], acc[fm][fn][3]);
        }
    }
}

// ---------------------------------------------------------------------------
// Kernel 2: fold split-K partials + bias + gates + n_t + m_t + divisor.
// One block per batch row b.
// ---------------------------------------------------------------------------
__global__ __launch_bounds__(256) void gates_kernel(BiasArgs ba,
                                                    const float* __restrict__ n_in,
                                                    const float* __restrict__ m_in,
                                                    float* __restrict__ out) {
    __shared__ float sbuf[8];
    const int b   = blockIdx.x;
    const int tid = threadIdx.x;

    float* __restrict__ outN = out + (size_t)BH + (size_t)BB * HH * HH;
    float* __restrict__ outM = outN + BH;

    float local = 0.f;
#pragma unroll
    for (int j = 0; j < 4; ++j) {
        int h   = tid + j * 256;
        int idx = b * HH + h;

        float zz[6];
#pragma unroll
        for (int g = 0; g < 6; ++g) {
            float s = ba.b[g][h];
#pragma unroll
            for (int z = 0; z < KSPLIT; ++z)
                s += g_part[((size_t)z * 6 + g) * BH + idx];
            zz[g] = s;
        }
        float it = zz[0];
        float ft = zz[1];
        float ot = zz[2];
        float qv = zz[3];
        float kv = zz[4] * 0.03125f;   // 1/sqrt(1024)
        float vv = zz[5];

        float f_sig = 1.f / (1.f + expf(-ft));
        float o_sig = 1.f / (1.f + expf(-ot));
        float ls = (ft >= 0.f) ? -log1pf(expf(-ft)) : (ft - log1pf(expf(ft)));
        float mt = fmaxf(ls + m_in[idx], it);
        float ip = expf(it - mt);
        float nt = f_sig * n_in[idx] + ip * kv;

        g_f[idx]   = f_sig;
        g_o[idx]   = o_sig;
        g_ipv[idx] = ip * vv;
        g_lin[3 * BH + idx] = qv;
        g_lin[4 * BH + idx] = kv;

        outN[idx] = nt;
        outM[idx] = mt;
        local += nt * qv;
    }

#pragma unroll
    for (int off = 16; off > 0; off >>= 1)
        local += __shfl_down_sync(0xffffffffu, local, off);
    int lane = tid & 31, w = tid >> 5;
    if (lane == 0) sbuf[w] = local;
    __syncthreads();
    if (w == 0) {
        float v = (lane < 8) ? sbuf[lane] : 0.f;
#pragma unroll
        for (int off = 4; off > 0; off >>= 1)
            v += __shfl_down_sync(0xffffffffu, v, off);
        if (lane == 0) g_div[b] = fmaxf(fabsf(v), 1.f);
    }
}

// ---------------------------------------------------------------------------
// Kernel 3: fused C update + h.  One warp per row, 16 rows per block (512 thr).
//   C_t[b,r,j] = f[b,r]*C[b,r,j] + ipv[b,r] * k[b,j]
//   h[b,r]     = o[b,r] * dot(C_t[b,r,:], q[b,:]) / div[b]
// ---------------------------------------------------------------------------
__global__ __launch_bounds__(512) void update_kernel(const float* __restrict__ C,
                                                     float* __restrict__ out) {
    __shared__ float4 ks[256], qs[256];
    const int tid  = threadIdx.x;
    const int lane = tid & 31;
    const int b    = blockIdx.x >> 6;                 // 64 blocks per batch
    const int row  = blockIdx.x * 16 + (tid >> 5);    // this warp's row

    if (tid < 256)
        ks[tid] = reinterpret_cast<const float4*>(g_lin + 4 * BH + b * HH)[tid];
    else
        qs[tid - 256] = reinterpret_cast<const float4*>(g_lin + 3 * BH + b * HH)[tid - 256];
    __syncthreads();

    const float f   = g_f[row];
    const float ipv = g_ipv[row];

    const float4* __restrict__ Cr = reinterpret_cast<const float4*>(C + (size_t)row * HH);
    float4* __restrict__ Or = reinterpret_cast<float4*>(out + (size_t)BH + (size_t)row * HH);

    float4 c4[8];
#pragma unroll
    for (int j = 0; j < 8; ++j)
        c4[j] = __ldcs(Cr + j * 32 + lane);

    float dot = 0.f;
#pragma unroll
    for (int j = 0; j < 8; ++j) {
        float4 k4 = ks[j * 32 + lane];
        float4 q4 = qs[j * 32 + lane];
        float4 o;
        o.x = fmaf(f, c4[j].x, ipv * k4.x);
        o.y = fmaf(f, c4[j].y, ipv * k4.y);
        o.z = fmaf(f, c4[j].z, ipv * k4.z);
        o.w = fmaf(f, c4[j].w, ipv * k4.w);
        __stcs(Or + j * 32 + lane, o);
        dot = fmaf(o.x, q4.x, dot);
        dot = fmaf(o.y, q4.y, dot);
        dot = fmaf(o.z, q4.z, dot);
        dot = fmaf(o.w, q4.w, dot);
    }

#pragma unroll
    for (int off = 16; off > 0; off >>= 1)
        dot += __shfl_down_sync(0xffffffffu, dot, off);
    if (lane == 0)
        out[row] = g_o[row] * dot / g_div[b];
}

// ---------------------------------------------------------------------------
// Launch
// ---------------------------------------------------------------------------
extern "C" void kernel_launch(void* const* d_in, const int* in_sizes, int n_in,
                              void* d_out, int out_size) {
    const float* x = (const float*)d_in[0];
    const float* C = (const float*)d_in[1];
    const float* n = (const float*)d_in[2];
    const float* m = (const float*)d_in[3];

    GemmArgs ga;
    BiasArgs ba;
    for (int g = 0; g < 6; ++g) {
        ga.W[g] = (const float*)d_in[4 + 2 * g];
        ba.b[g] = (const float*)d_in[5 + 2 * g];
    }

    float* out = (float*)d_out;

    gemm_kernel<<<dim3(8, 6, KSPLIT), 256>>>(x, ga);
    gates_kernel<<<BB, 256>>>(ba, n, m, out);
    update_kernel<<<BB * HH / 16, 512>>>(C, out);
}

// round 9
// speedup vs baseline: 1.7717x; 1.0052x over previous
#include <cuda_runtime.h>
#include <math.h>
#include <stdint.h>

#define BB 64
#define HH 1024
#define INN 1024
#define BH (BB * HH)
#define KSPLIT 8
#define KSLICE (INN / KSPLIT)   // 128
#define NT (KSLICE / 32)        // 4 stages of BK=32

// Scratch (device globals — no allocations allowed).
__device__ float g_part[KSPLIT * 6 * BH];
__device__ float g_lin[6 * BH];
__device__ float g_f[BH];
__device__ float g_o[BH];
__device__ float g_ipv[BH];   // i' * v  (v with bias)
__device__ float g_div[BB];

struct GemmArgs { const float* W[6]; };
struct BiasArgs { const float* b[6]; };

__device__ __forceinline__ uint32_t f2tf(float f) {
    uint32_t r;
    asm("cvt.rna.tf32.f32 %0, %1;" : "=r"(r) : "f"(f));
    return r;
}

__device__ __forceinline__ void mma_tf32(float c[4],
                                         uint32_t a0, uint32_t a1, uint32_t a2, uint32_t a3,
                                         uint32_t b0, uint32_t b1) {
    asm("mma.sync.aligned.m16n8k8.row.col.f32.tf32.tf32.f32 "
        "{%0,%1,%2,%3},{%4,%5,%6,%7},{%8,%9},{%0,%1,%2,%3};"
        : "+f"(c[0]), "+f"(c[1]), "+f"(c[2]), "+f"(c[3])
        : "r"(a0), "r"(a1), "r"(a2), "r"(a3), "r"(b0), "r"(b1));
}

// ---------------------------------------------------------------------------
// Kernel 1: six fused GEMMs on tf32 tensor cores, split-K=8.
// Block tile 64(M) x 128(N) x 128(Kslice); 8 warps as 2(M) x 4(N), warp tile
// 32x32.  x for the WHOLE Kslice is staged once into 4 smem panels (rounded
// cvt); only W streams per stage through a distance-1 register prefetch into
// a double buffer.  One __syncthreads per stage.
// ---------------------------------------------------------------------------
__global__ __launch_bounds__(256, 3) void gemm_kernel(const float* __restrict__ x, GemmArgs args) {
    __shared__ uint32_t xs[NT][64 * 32];   // 32 KB, filled once
    __shared__ uint32_t ws[2][128 * 32];   // 32 KB double buffer

    const int g    = blockIdx.y;
    const int n0   = blockIdx.x * 128;
    const int z    = blockIdx.z;
    const int kf0  = z * (KSLICE / 4);     // base in float4 units (32)
    const float* __restrict__ W = args.W[g];

    const int tid  = threadIdx.x;
    const int lane = tid & 31;
    const int warp = tid >> 5;
    const int wm   = warp & 1;    // M-warp: rows wm*32
    const int wn   = warp >> 1;   // N-warp: cols wn*32

    const float4* __restrict__ x4 = reinterpret_cast<const float4*>(x);
    const float4* __restrict__ W4 = reinterpret_cast<const float4*>(W);

    const int fr  = tid >> 3;     // fill row 0..31
    const int fc  = tid & 7;      // fill float4-col 0..7
    const int fsw = (fc * 4) ^ ((fr & 7) << 2);   // row-xor swizzle (r, r+32 same)

    auto cvt4 = [](float4 v) {
        return make_uint4(f2tf(v.x), f2tf(v.y), f2tf(v.z), f2tf(v.w));
    };

    // ---- preamble: W stage 0 + entire x slice ----
    {
        float4 w0[4];
#pragma unroll
        for (int i = 0; i < 4; ++i)
            w0[i] = W4[(size_t)(n0 + fr + 32 * i) * 256 + kf0 + fc];

        float4 xr[2 * NT];
#pragma unroll
        for (int t = 0; t < NT; ++t) {
            xr[2 * t]     = x4[(size_t)fr * 256 + kf0 + t * 8 + fc];
            xr[2 * t + 1] = x4[(size_t)(fr + 32) * 256 + kf0 + t * 8 + fc];
        }
#pragma unroll
        for (int t = 0; t < NT; ++t) {
            *reinterpret_cast<uint4*>(&xs[t][fr * 32 + fsw])        = cvt4(xr[2 * t]);
            *reinterpret_cast<uint4*>(&xs[t][(fr + 32) * 32 + fsw]) = cvt4(xr[2 * t + 1]);
        }
#pragma unroll
        for (int i = 0; i < 4; ++i)
            *reinterpret_cast<uint4*>(&ws[0][(fr + 32 * i) * 32 + fsw]) = cvt4(w0[i]);
    }
    __syncthreads();

    float acc[2][4][4];
#pragma unroll
    for (int i = 0; i < 2; ++i)
#pragma unroll
        for (int j = 0; j < 4; ++j)
#pragma unroll
            for (int l = 0; l < 4; ++l) acc[i][j][l] = 0.f;

    const int q  = lane >> 2;     // 0..7
    const int tt = lane & 3;      // 0..3
    const int sw = q << 2;

    int acol[4], acolx[4];
#pragma unroll
    for (int kk = 0; kk < 4; ++kk) {
        acol[kk]  = ((kk * 8) + tt) ^ sw;
        acolx[kk] = acol[kk] ^ 4;
    }
    const int arow = (wm * 32 + q) * 32;
    const int brow = (wn * 32 + q) * 32;

#pragma unroll
    for (int t = 0; t < NT; ++t) {
        // distance-1 prefetch of next W stage (lands during this stage's MMAs)
        float4 wn4[4];
        if (t < NT - 1) {
            int k4n = kf0 + (t + 1) * 8;
#pragma unroll
            for (int i = 0; i < 4; ++i)
                wn4[i] = W4[(size_t)(n0 + fr + 32 * i) * 256 + k4n + fc];
        }

        const uint32_t* __restrict__ X  = xs[t];
        const uint32_t* __restrict__ Wt = ws[t & 1];
#pragma unroll
        for (int kk = 0; kk < 4; ++kk) {
            const int c = acol[kk], cx = acolx[kk];
            uint32_t a00 = X[arow + c];
            uint32_t a01 = X[arow + 8 * 32 + c];
            uint32_t a02 = X[arow + cx];
            uint32_t a03 = X[arow + 8 * 32 + cx];
            uint32_t a10 = X[arow + 16 * 32 + c];
            uint32_t a11 = X[arow + 24 * 32 + c];
            uint32_t a12 = X[arow + 16 * 32 + cx];
            uint32_t a13 = X[arow + 24 * 32 + cx];
            uint32_t b00 = Wt[brow + c],           b01 = Wt[brow + cx];
            uint32_t b10 = Wt[brow + 8 * 32 + c],  b11 = Wt[brow + 8 * 32 + cx];
            uint32_t b20 = Wt[brow + 16 * 32 + c], b21 = Wt[brow + 16 * 32 + cx];
            uint32_t b30 = Wt[brow + 24 * 32 + c], b31 = Wt[brow + 24 * 32 + cx];

            mma_tf32(acc[0][0], a00, a01, a02, a03, b00, b01);
            mma_tf32(acc[0][1], a00, a01, a02, a03, b10, b11);
            mma_tf32(acc[0][2], a00, a01, a02, a03, b20, b21);
            mma_tf32(acc[0][3], a00, a01, a02, a03, b30, b31);
            mma_tf32(acc[1][0], a10, a11, a12, a13, b00, b01);
            mma_tf32(acc[1][1], a10, a11, a12, a13, b10, b11);
            mma_tf32(acc[1][2], a10, a11, a12, a13, b20, b21);
            mma_tf32(acc[1][3], a10, a11, a12, a13, b30, b31);
        }

        if (t < NT - 1) {
            const int nb = (t + 1) & 1;
#pragma unroll
            for (int i = 0; i < 4; ++i)
                *reinterpret_cast<uint4*>(&ws[nb][(fr + 32 * i) * 32 + fsw]) = cvt4(wn4[i]);
            __syncthreads();
        }
    }

    // epilogue: write partials
    float* __restrict__ Z = g_part + ((size_t)z * 6 + g) * BH;
#pragma unroll
    for (int fm = 0; fm < 2; ++fm) {
#pragma unroll
        for (int fn = 0; fn < 4; ++fn) {
            const int r0 = wm * 32 + fm * 16 + q;
            const int c0 = n0 + wn * 32 + fn * 8 + 2 * tt;
            *reinterpret_cast<float2*>(&Z[(size_t)r0 * HH + c0]) =
                make_float2(acc[fm][fn][0], acc[fm][fn][1]);
            *reinterpret_cast<float2*>(&Z[(size_t)(r0 + 8) * HH + c0]) =
                make_float2(acc[fm][fn][2], acc[fm][fn][3]);
        }
    }
}

// ---------------------------------------------------------------------------
// Kernel 2: fold split-K partials + bias + gates + n_t + m_t + divisor.
// ---------------------------------------------------------------------------
__global__ __launch_bounds__(256) void gates_kernel(BiasArgs ba,
                                                    const float* __restrict__ n_in,
                                                    const float* __restrict__ m_in,
                                                    float* __restrict__ out) {
    __shared__ float sbuf[8];
    const int b   = blockIdx.x;
    const int tid = threadIdx.x;

    float* __restrict__ outN = out + (size_t)BH + (size_t)BB * HH * HH;
    float* __restrict__ outM = outN + BH;

    float local = 0.f;
#pragma unroll
    for (int j = 0; j < 4; ++j) {
        int h   = tid + j * 256;
        int idx = b * HH + h;

        float zz[6];
#pragma unroll
        for (int g = 0; g < 6; ++g) {
            float s = ba.b[g][h];
#pragma unroll
            for (int z = 0; z < KSPLIT; ++z)
                s += g_part[((size_t)z * 6 + g) * BH + idx];
            zz[g] = s;
        }
        float it = zz[0];
        float ft = zz[1];
        float ot = zz[2];
        float qv = zz[3];
        float kv = zz[4] * 0.03125f;   // 1/sqrt(1024)
        float vv = zz[5];

        float f_sig = 1.f / (1.f + expf(-ft));
        float o_sig = 1.f / (1.f + expf(-ot));
        float ls = (ft >= 0.f) ? -log1pf(expf(-ft)) : (ft - log1pf(expf(ft)));
        float mt = fmaxf(ls + m_in[idx], it);
        float ip = expf(it - mt);
        float nt = f_sig * n_in[idx] + ip * kv;

        g_f[idx]   = f_sig;
        g_o[idx]   = o_sig;
        g_ipv[idx] = ip * vv;
        g_lin[3 * BH + idx] = qv;
        g_lin[4 * BH + idx] = kv;

        outN[idx] = nt;
        outM[idx] = mt;
        local += nt * qv;
    }

#pragma unroll
    for (int off = 16; off > 0; off >>= 1)
        local += __shfl_down_sync(0xffffffffu, local, off);
    int lane = tid & 31, w = tid >> 5;
    if (lane == 0) sbuf[w] = local;
    __syncthreads();
    if (w == 0) {
        float v = (lane < 8) ? sbuf[lane] : 0.f;
#pragma unroll
        for (int off = 4; off > 0; off >>= 1)
            v += __shfl_down_sync(0xffffffffu, v, off);
        if (lane == 0) g_div[b] = fmaxf(fabsf(v), 1.f);
    }
}

// ---------------------------------------------------------------------------
// Kernel 3: fused C update + h.  One warp per row, 16 rows per block (512 thr).
// ---------------------------------------------------------------------------
__global__ __launch_bounds__(512) void update_kernel(const float* __restrict__ C,
                                                     float* __restrict__ out) {
    __shared__ float4 ks[256], qs[256];
    const int tid  = threadIdx.x;
    const int lane = tid & 31;
    const int b    = blockIdx.x >> 6;                 // 64 blocks per batch
    const int row  = blockIdx.x * 16 + (tid >> 5);    // this warp's row

    if (tid < 256)
        ks[tid] = reinterpret_cast<const float4*>(g_lin + 4 * BH + b * HH)[tid];
    else
        qs[tid - 256] = reinterpret_cast<const float4*>(g_lin + 3 * BH + b * HH)[tid - 256];
    __syncthreads();

    const float f   = g_f[row];
    const float ipv = g_ipv[row];

    const float4* __restrict__ Cr = reinterpret_cast<const float4*>(C + (size_t)row * HH);
    float4* __restrict__ Or = reinterpret_cast<float4*>(out + (size_t)BH + (size_t)row * HH);

    float4 c4[8];
#pragma unroll
    for (int j = 0; j < 8; ++j)
        c4[j] = __ldcs(Cr + j * 32 + lane);

    float dot = 0.f;
#pragma unroll
    for (int j = 0; j < 8; ++j) {
        float4 k4 = ks[j * 32 + lane];
        float4 q4 = qs[j * 32 + lane];
        float4 o;
        o.x = fmaf(f, c4[j].x, ipv * k4.x);
        o.y = fmaf(f, c4[j].y, ipv * k4.y);
        o.z = fmaf(f, c4[j].z, ipv * k4.z);
        o.w = fmaf(f, c4[j].w, ipv * k4.w);
        __stcs(Or + j * 32 + lane, o);
        dot = fmaf(o.x, q4.x, dot);
        dot = fmaf(o.y, q4.y, dot);
        dot = fmaf(o.z, q4.z, dot);
        dot = fmaf(o.w, q4.w, dot);
    }

#pragma unroll
    for (int off = 16; off > 0; off >>= 1)
        dot += __shfl_down_sync(0xffffffffu, dot, off);
    if (lane == 0)
        out[row] = g_o[row] * dot / g_div[b];
}

// ---------------------------------------------------------------------------
// Launch
// ---------------------------------------------------------------------------
extern "C" void kernel_launch(void* const* d_in, const int* in_sizes, int n_in,
                              void* d_out, int out_size) {
    const float* x = (const float*)d_in[0];
    const float* C = (const float*)d_in[1];
    const float* n = (const float*)d_in[2];
    const float* m = (const float*)d_in[3];

    GemmArgs ga;
    BiasArgs ba;
    for (int g = 0; g < 6; ++g) {
        ga.W[g] = (const float*)d_in[4 + 2 * g];
        ba.b[g] = (const float*)d_in[5 + 2 * g];
    }

    float* out = (float*)d_out;

    gemm_kernel<<<dim3(8, 6, KSPLIT), 256>>>(x, ga);
    gates_kernel<<<BB, 256>>>(ba, n, m, out);
    update_kernel<<<BB * HH / 16, 512>>>(C, out);
}

// round 11
// speedup vs baseline: 1.7750x; 1.0018x over previous
#include <cuda_runtime.h>
#include <math.h>
#include <stdint.h>

#define BB 64
#define HH 1024
#define INN 1024
#define BH (BB * HH)
#define KSPLIT 8
#define KSLICE (INN / KSPLIT)   // 128
#define NT (KSLICE / 32)        // 4 stages of BK=32

// Scratch (device globals — no allocations allowed).
__device__ float g_part[KSPLIT * 6 * BH];
__device__ float g_lin[6 * BH];
__device__ float g_f[BH];
__device__ float g_o[BH];
__device__ float g_ipv[BH];   // i' * v  (v with bias)
__device__ float g_div[BB];

struct GemmArgs { const float* W[6]; };
struct BiasArgs { const float* b[6]; };

__device__ __forceinline__ uint32_t f2tf(float f) {
    uint32_t r;
    asm("cvt.rna.tf32.f32 %0, %1;" : "=r"(r) : "f"(f));
    return r;
}

__device__ __forceinline__ void mma_tf32(float c[4],
                                         uint32_t a0, uint32_t a1, uint32_t a2, uint32_t a3,
                                         uint32_t b0, uint32_t b1) {
    asm("mma.sync.aligned.m16n8k8.row.col.f32.tf32.tf32.f32 "
        "{%0,%1,%2,%3},{%4,%5,%6,%7},{%8,%9},{%0,%1,%2,%3};"
        : "+f"(c[0]), "+f"(c[1]), "+f"(c[2]), "+f"(c[3])
        : "r"(a0), "r"(a1), "r"(a2), "r"(a3), "r"(b0), "r"(b1));
}

// ---------------------------------------------------------------------------
// Kernel 1: six fused GEMMs on tf32 tensor cores, split-K=8.
// Block tile 64(M) x 128(N) x 128(Kslice); 8 warps as 2(M) x 4(N), warp tile
// 32x32.  The ENTIRE K-slice (x: 32KB, W: 64KB) is staged into smem in one
// preamble with all 24 vec4 LDGs issued back-to-back (single latency
// exposure), then 128 MMAs/warp run with no global loads and no syncs.
// ---------------------------------------------------------------------------
__global__ __launch_bounds__(256, 2) void gemm_kernel(const float* __restrict__ x, GemmArgs args) {
    __shared__ uint32_t xs[NT][64 * 32];    // 32 KB
    __shared__ uint32_t ws[NT][128 * 32];   // 64 KB

    const int g    = blockIdx.y;
    const int n0   = blockIdx.x * 128;
    const int z    = blockIdx.z;
    const int kf0  = z * (KSLICE / 4);      // base in float4 units (32)
    const float* __restrict__ W = args.W[g];

    const int tid  = threadIdx.x;
    const int lane = tid & 31;
    const int warp = tid >> 5;
    const int wm   = warp & 1;    // M-warp: rows wm*32
    const int wn   = warp >> 1;   // N-warp: cols wn*32

    const float4* __restrict__ x4 = reinterpret_cast<const float4*>(x);
    const float4* __restrict__ W4 = reinterpret_cast<const float4*>(W);

    const int fr  = tid >> 3;     // fill row 0..31
    const int fc  = tid & 7;      // fill float4-col 0..7
    const int fsw = (fc * 4) ^ ((fr & 7) << 2);   // row-xor swizzle (r, r+32 same)

    auto cvt4 = [](float4 v) {
        return make_uint4(f2tf(v.x), f2tf(v.y), f2tf(v.z), f2tf(v.w));
    };

    // ---- preamble: issue ALL global loads for the slice back-to-back ----
    {
        float4 xr[2 * NT];
#pragma unroll
        for (int t = 0; t < NT; ++t) {
            xr[2 * t]     = x4[(size_t)fr * 256 + kf0 + t * 8 + fc];
            xr[2 * t + 1] = x4[(size_t)(fr + 32) * 256 + kf0 + t * 8 + fc];
        }
        float4 wr[4 * NT];
#pragma unroll
        for (int t = 0; t < NT; ++t)
#pragma unroll
            for (int i = 0; i < 4; ++i)
                wr[t * 4 + i] = W4[(size_t)(n0 + fr + 32 * i) * 256 + kf0 + t * 8 + fc];

#pragma unroll
        for (int t = 0; t < NT; ++t) {
            *reinterpret_cast<uint4*>(&xs[t][fr * 32 + fsw])        = cvt4(xr[2 * t]);
            *reinterpret_cast<uint4*>(&xs[t][(fr + 32) * 32 + fsw]) = cvt4(xr[2 * t + 1]);
        }
#pragma unroll
        for (int t = 0; t < NT; ++t)
#pragma unroll
            for (int i = 0; i < 4; ++i)
                *reinterpret_cast<uint4*>(&ws[t][(fr + 32 * i) * 32 + fsw]) = cvt4(wr[t * 4 + i]);
    }
    __syncthreads();

    float acc[2][4][4];
#pragma unroll
    for (int i = 0; i < 2; ++i)
#pragma unroll
        for (int j = 0; j < 4; ++j)
#pragma unroll
            for (int l = 0; l < 4; ++l) acc[i][j][l] = 0.f;

    const int q  = lane >> 2;     // 0..7
    const int tt = lane & 3;      // 0..3
    const int sw = q << 2;

    int acol[4], acolx[4];
#pragma unroll
    for (int kk = 0; kk < 4; ++kk) {
        acol[kk]  = ((kk * 8) + tt) ^ sw;
        acolx[kk] = acol[kk] ^ 4;
    }
    const int arow = (wm * 32 + q) * 32;
    const int brow = (wn * 32 + q) * 32;

    // ---- pure-MMA mainloop: no global loads, no syncs ----
#pragma unroll
    for (int t = 0; t < NT; ++t) {
        const uint32_t* __restrict__ X  = xs[t];
        const uint32_t* __restrict__ Wt = ws[t];
#pragma unroll
        for (int kk = 0; kk < 4; ++kk) {
            const int c = acol[kk], cx = acolx[kk];
            uint32_t a00 = X[arow + c];
            uint32_t a01 = X[arow + 8 * 32 + c];
            uint32_t a02 = X[arow + cx];
            uint32_t a03 = X[arow + 8 * 32 + cx];
            uint32_t a10 = X[arow + 16 * 32 + c];
            uint32_t a11 = X[arow + 24 * 32 + c];
            uint32_t a12 = X[arow + 16 * 32 + cx];
            uint32_t a13 = X[arow + 24 * 32 + cx];
            uint32_t b00 = Wt[brow + c],           b01 = Wt[brow + cx];
            uint32_t b10 = Wt[brow + 8 * 32 + c],  b11 = Wt[brow + 8 * 32 + cx];
            uint32_t b20 = Wt[brow + 16 * 32 + c], b21 = Wt[brow + 16 * 32 + cx];
            uint32_t b30 = Wt[brow + 24 * 32 + c], b31 = Wt[brow + 24 * 32 + cx];

            mma_tf32(acc[0][0], a00, a01, a02, a03, b00, b01);
            mma_tf32(acc[0][1], a00, a01, a02, a03, b10, b11);
            mma_tf32(acc[0][2], a00, a01, a02, a03, b20, b21);
            mma_tf32(acc[0][3], a00, a01, a02, a03, b30, b31);
            mma_tf32(acc[1][0], a10, a11, a12, a13, b00, b01);
            mma_tf32(acc[1][1], a10, a11, a12, a13, b10, b11);
            mma_tf32(acc[1][2], a10, a11, a12, a13, b20, b21);
            mma_tf32(acc[1][3], a10, a11, a12, a13, b30, b31);
        }
    }

    // epilogue: write partials
    float* __restrict__ Z = g_part + ((size_t)z * 6 + g) * BH;
#pragma unroll
    for (int fm = 0; fm < 2; ++fm) {
#pragma unroll
        for (int fn = 0; fn < 4; ++fn) {
            const int r0 = wm * 32 + fm * 16 + q;
            const int c0 = n0 + wn * 32 + fn * 8 + 2 * tt;
            *reinterpret_cast<float2*>(&Z[(size_t)r0 * HH + c0]) =
                make_float2(acc[fm][fn][0], acc[fm][fn][1]);
            *reinterpret_cast<float2*>(&Z[(size_t)(r0 + 8) * HH + c0]) =
                make_float2(acc[fm][fn][2], acc[fm][fn][3]);
        }
    }
}

// ---------------------------------------------------------------------------
// Kernel 2: fold split-K partials + bias + gates + n_t + m_t + divisor.
// ---------------------------------------------------------------------------
__global__ __launch_bounds__(256) void gates_kernel(BiasArgs ba,
                                                    const float* __restrict__ n_in,
                                                    const float* __restrict__ m_in,
                                                    float* __restrict__ out) {
    __shared__ float sbuf[8];
    const int b   = blockIdx.x;
    const int tid = threadIdx.x;

    float* __restrict__ outN = out + (size_t)BH + (size_t)BB * HH * HH;
    float* __restrict__ outM = outN + BH;

    float local = 0.f;
#pragma unroll
    for (int j = 0; j < 4; ++j) {
        int h   = tid + j * 256;
        int idx = b * HH + h;

        float zz[6];
#pragma unroll
        for (int g = 0; g < 6; ++g) {
            float s = ba.b[g][h];
#pragma unroll
            for (int z = 0; z < KSPLIT; ++z)
                s += g_part[((size_t)z * 6 + g) * BH + idx];
            zz[g] = s;
        }
        float it = zz[0];
        float ft = zz[1];
        float ot = zz[2];
        float qv = zz[3];
        float kv = zz[4] * 0.03125f;   // 1/sqrt(1024)
        float vv = zz[5];

        float f_sig = 1.f / (1.f + expf(-ft));
        float o_sig = 1.f / (1.f + expf(-ot));
        float ls = (ft >= 0.f) ? -log1pf(expf(-ft)) : (ft - log1pf(expf(ft)));
        float mt = fmaxf(ls + m_in[idx], it);
        float ip = expf(it - mt);
        float nt = f_sig * n_in[idx] + ip * kv;

        g_f[idx]   = f_sig;
        g_o[idx]   = o_sig;
        g_ipv[idx] = ip * vv;
        g_lin[3 * BH + idx] = qv;
        g_lin[4 * BH + idx] = kv;

        outN[idx] = nt;
        outM[idx] = mt;
        local += nt * qv;
    }

#pragma unroll
    for (int off = 16; off > 0; off >>= 1)
        local += __shfl_down_sync(0xffffffffu, local, off);
    int lane = tid & 31, w = tid >> 5;
    if (lane == 0) sbuf[w] = local;
    __syncthreads();
    if (w == 0) {
        float v = (lane < 8) ? sbuf[lane] : 0.f;
#pragma unroll
        for (int off = 4; off > 0; off >>= 1)
            v += __shfl_down_sync(0xffffffffu, v, off);
        if (lane == 0) g_div[b] = fmaxf(fabsf(v), 1.f);
    }
}

// ---------------------------------------------------------------------------
// Kernel 3: fused C update + h.  One warp per row, 32 rows per block (1024 thr).
//   C_t[b,r,j] = f[b,r]*C[b,r,j] + ipv[b,r] * k[b,j]
//   h[b,r]     = o[b,r] * dot(C_t[b,r,:], q[b,:]) / div[b]
// ---------------------------------------------------------------------------
__global__ __launch_bounds__(1024) void update_kernel(const float* __restrict__ C,
                                                      float* __restrict__ out) {
    __shared__ float4 ks[256], qs[256];
    const int tid  = threadIdx.x;
    const int lane = tid & 31;
    const int b    = blockIdx.x >> 5;                 // 32 blocks per batch
    const int row  = blockIdx.x * 32 + (tid >> 5);    // this warp's row

    if (tid < 256) {
        ks[tid] = reinterpret_cast<const float4*>(g_lin + 4 * BH + b * HH)[tid];
    } else if (tid < 512) {
        qs[tid - 256] = reinterpret_cast<const float4*>(g_lin + 3 * BH + b * HH)[tid - 256];
    }
    __syncthreads();

    const float f   = g_f[row];
    const float ipv = g_ipv[row];

    const float4* __restrict__ Cr = reinterpret_cast<const float4*>(C + (size_t)row * HH);
    float4* __restrict__ Or = reinterpret_cast<float4*>(out + (size_t)BH + (size_t)row * HH);

    float4 c4[8];
#pragma unroll
    for (int j = 0; j < 8; ++j)
        c4[j] = __ldcs(Cr + j * 32 + lane);

    float dot = 0.f;
#pragma unroll
    for (int j = 0; j < 8; ++j) {
        float4 k4 = ks[j * 32 + lane];
        float4 q4 = qs[j * 32 + lane];
        float4 o;
        o.x = fmaf(f, c4[j].x, ipv * k4.x);
        o.y = fmaf(f, c4[j].y, ipv * k4.y);
        o.z = fmaf(f, c4[j].z, ipv * k4.z);
        o.w = fmaf(f, c4[j].w, ipv * k4.w);
        __stcs(Or + j * 32 + lane, o);
        dot = fmaf(o.x, q4.x, dot);
        dot = fmaf(o.y, q4.y, dot);
        dot = fmaf(o.z, q4.z, dot);
        dot = fmaf(o.w, q4.w, dot);
    }

#pragma unroll
    for (int off = 16; off > 0; off >>= 1)
        dot += __shfl_down_sync(0xffffffffu, dot, off);
    if (lane == 0)
        out[row] = g_o[row] * dot / g_div[b];
}

// ---------------------------------------------------------------------------
// Launch
// ---------------------------------------------------------------------------
extern "C" void kernel_launch(void* const* d_in, const int* in_sizes, int n_in,
                              void* d_out, int out_size) {
    const float* x = (const float*)d_in[0];
    const float* C = (const float*)d_in[1];
    const float* n = (const float*)d_in[2];
    const float* m = (const float*)d_in[3];

    GemmArgs ga;
    BiasArgs ba;
    for (int g = 0; g < 6; ++g) {
        ga.W[g] = (const float*)d_in[4 + 2 * g];
        ba.b[g] = (const float*)d_in[5 + 2 * g];
    }

    float* out = (float*)d_out;

    gemm_kernel<<<dim3(8, 6, KSPLIT), 256>>>(x, ga);
    gates_kernel<<<BB, 256>>>(ba, n, m, out);
    update_kernel<<<BB * HH / 32, 1024>>>(C, out);
}